// round 1
// baseline (speedup 1.0000x reference)
#include <cuda_runtime.h>
#include <cstdint>

// Problem constants
#define B_SZ   4
#define SEQ    2048
#define DMODEL 512
#define HEADS  8
#define HDIM   64
#define BH     (B_SZ*HEADS)          // 32
#define MROWS  (B_SZ*SEQ)            // 8192

// Scratch (static __device__ arrays: sanctioned alloc-free workaround)
__device__ float g_qkv[(size_t)24 * MROWS * HDIM];          // [g=3h+j][m][k]  50.3 MB
__device__ float g_sbuf[(size_t)BH * SEQ * SEQ];            // scores          512 MB
__device__ float g_obuf[(size_t)BH * SEQ * HDIM];           // attention out   16.8 MB
__device__ float g_rowm[(size_t)BH * SEQ];
__device__ float g_rowinvl[(size_t)BH * SEQ];

// ---------------------------------------------------------------------------
// Pass 1: QKV projection.  C(8192 x 1536) = X(8192 x 512) * W(512 x 1536)
// W element (d, c) with c=(3h+j)*64+k lives at kernel[(c>>6)*32768 + d*64 + (c&63)]
// Output scattered into g_qkv[(c>>6)][m][c&63].
// Tile 128x128, KT=32, 256 thr, 8x8 micro (interleaved m = tm + i*16).
// ---------------------------------------------------------------------------
__global__ __launch_bounds__(256) void qkv_gemm(const float* __restrict__ X,
                                                const float* __restrict__ W)
{
    __shared__ float As[128 * 36];   // [m][d], stride 36 => 2-way max conflicts
    __shared__ float Bs[32 * 132];   // [d][c], stride 132

    const int tid = threadIdx.x;
    const int m0 = blockIdx.y * 128;
    const int c0 = blockIdx.x * 128;
    const int tm = tid >> 4, tn = tid & 15;
    const int ar = tid >> 3, ac = (tid & 7) * 4;
    const int bdl = tid >> 5, bcl = (tid & 31) * 4;

    float acc[8][8];
#pragma unroll
    for (int i = 0; i < 8; i++)
#pragma unroll
        for (int j = 0; j < 8; j++) acc[i][j] = 0.f;

    for (int k0 = 0; k0 < DMODEL; k0 += 32) {
#pragma unroll
        for (int it = 0; it < 4; it++) {
            int r = ar + it * 32;
            float4 v = *(const float4*)(X + (size_t)(m0 + r) * DMODEL + k0 + ac);
            *(float4*)(As + r * 36 + ac) = v;
        }
#pragma unroll
        for (int it = 0; it < 4; it++) {
            int d = bdl + it * 8;
            int c = c0 + bcl;
            int g = c >> 6;
            float4 v = *(const float4*)(W + (size_t)g * (DMODEL * HDIM)
                                          + (size_t)(k0 + d) * HDIM + (c & 63));
            *(float4*)(Bs + d * 132 + bcl) = v;
        }
        __syncthreads();
#pragma unroll
        for (int d = 0; d < 32; d++) {
            float a[8], b[8];
#pragma unroll
            for (int i = 0; i < 8; i++) a[i] = As[(tm + i * 16) * 36 + d];
#pragma unroll
            for (int j = 0; j < 8; j++) b[j] = Bs[d * 132 + tn + j * 16];
#pragma unroll
            for (int i = 0; i < 8; i++)
#pragma unroll
                for (int j = 0; j < 8; j++) acc[i][j] += a[i] * b[j];
        }
        __syncthreads();
    }

#pragma unroll
    for (int i = 0; i < 8; i++) {
        int m = m0 + tm + i * 16;
#pragma unroll
        for (int j = 0; j < 8; j++) {
            int c = c0 + tn + j * 16;
            int g = c >> 6, k = c & 63;
            g_qkv[((size_t)g * MROWS + m) * HDIM + k] = acc[i][j];
        }
    }
}

// ---------------------------------------------------------------------------
// Pass 2: S = Q * K^T * (1/8)  per (b,h).  NT GEMM, M=N=2048, inner=64.
// ---------------------------------------------------------------------------
__global__ __launch_bounds__(256) void qk_gemm()
{
    __shared__ float As[128 * 36];
    __shared__ float Bs[128 * 36];

    const int z = blockIdx.z;
    const int b = z >> 3, h = z & 7;
    const float* Q  = g_qkv + ((size_t)(3 * h)     * MROWS + (size_t)b * SEQ) * HDIM;
    const float* Kp = g_qkv + ((size_t)(3 * h + 1) * MROWS + (size_t)b * SEQ) * HDIM;
    float* Sp = g_sbuf + (size_t)z * SEQ * SEQ;

    const int tid = threadIdx.x;
    const int m0 = blockIdx.y * 128, n0 = blockIdx.x * 128;
    const int tm = tid >> 4, tn = tid & 15;
    const int ar = tid >> 3, ac = (tid & 7) * 4;

    float acc[8][8];
#pragma unroll
    for (int i = 0; i < 8; i++)
#pragma unroll
        for (int j = 0; j < 8; j++) acc[i][j] = 0.f;

    for (int k0 = 0; k0 < HDIM; k0 += 32) {
#pragma unroll
        for (int it = 0; it < 4; it++) {
            int r = ar + it * 32;
            *(float4*)(As + r * 36 + ac) = *(const float4*)(Q  + (size_t)(m0 + r) * HDIM + k0 + ac);
            *(float4*)(Bs + r * 36 + ac) = *(const float4*)(Kp + (size_t)(n0 + r) * HDIM + k0 + ac);
        }
        __syncthreads();
#pragma unroll
        for (int d = 0; d < 32; d++) {
            float a[8], bb[8];
#pragma unroll
            for (int i = 0; i < 8; i++) a[i]  = As[(tm + i * 16) * 36 + d];
#pragma unroll
            for (int j = 0; j < 8; j++) bb[j] = Bs[(tn + j * 16) * 36 + d];
#pragma unroll
            for (int i = 0; i < 8; i++)
#pragma unroll
                for (int j = 0; j < 8; j++) acc[i][j] += a[i] * bb[j];
        }
        __syncthreads();
    }

#pragma unroll
    for (int i = 0; i < 8; i++) {
        int m = m0 + tm + i * 16;
#pragma unroll
        for (int j = 0; j < 8; j++)
            Sp[(size_t)m * SEQ + n0 + tn + j * 16] = acc[i][j] * 0.125f;
    }
}

// ---------------------------------------------------------------------------
// Pass 3: per-row softmax stats: rowm = max, rowinvl = 1/sum(exp(s - max))
// One warp per row (2048 elems).
// ---------------------------------------------------------------------------
__global__ __launch_bounds__(256) void softmax_stats()
{
    const int r = blockIdx.x * 8 + (threadIdx.x >> 5);
    const int lane = threadIdx.x & 31;
    const float4* row4 = (const float4*)(g_sbuf + (size_t)r * SEQ);

    float mx = -1e30f;
    for (int j = lane; j < SEQ / 4; j += 32) {
        float4 v = row4[j];
        mx = fmaxf(mx, fmaxf(fmaxf(v.x, v.y), fmaxf(v.z, v.w)));
    }
#pragma unroll
    for (int o = 16; o; o >>= 1) mx = fmaxf(mx, __shfl_xor_sync(0xffffffffu, mx, o));

    float s = 0.f;
    for (int j = lane; j < SEQ / 4; j += 32) {
        float4 v = row4[j];
        s += __expf(v.x - mx) + __expf(v.y - mx) + __expf(v.z - mx) + __expf(v.w - mx);
    }
#pragma unroll
    for (int o = 16; o; o >>= 1) s += __shfl_xor_sync(0xffffffffu, s, o);

    if (lane == 0) {
        g_rowm[r] = mx;
        g_rowinvl[r] = 1.f / s;
    }
}

// ---------------------------------------------------------------------------
// Pass 4: O = softmax(S) * V per (b,h).  NN GEMM M=2048, N=64, inner=2048.
// exp(s - rowmax) applied in the A-tile loader; 1/l applied in epilogue.
// Tile 128x64, 8x4 micro.
// ---------------------------------------------------------------------------
__global__ __launch_bounds__(256) void pv_gemm()
{
    __shared__ float As[128 * 36];
    __shared__ float Bs[32 * 68];
    __shared__ float ms[128];

    const int z = blockIdx.y;
    const int b = z >> 3, h = z & 7;
    const float* Sp = g_sbuf + (size_t)z * SEQ * SEQ;
    const float* V  = g_qkv + ((size_t)(3 * h + 2) * MROWS + (size_t)b * SEQ) * HDIM;

    const int tid = threadIdx.x;
    const int m0 = blockIdx.x * 128;
    if (tid < 128) ms[tid] = g_rowm[(size_t)z * SEQ + m0 + tid];
    __syncthreads();

    const int tm = tid >> 4, tn = tid & 15;
    const int ar = tid >> 3, ac = (tid & 7) * 4;
    const int br = tid >> 4, bc = (tid & 15) * 4;

    float acc[8][4];
#pragma unroll
    for (int i = 0; i < 8; i++)
#pragma unroll
        for (int j = 0; j < 4; j++) acc[i][j] = 0.f;

    for (int k0 = 0; k0 < SEQ; k0 += 32) {
#pragma unroll
        for (int it = 0; it < 4; it++) {
            int r = ar + it * 32;
            float4 v = *(const float4*)(Sp + (size_t)(m0 + r) * SEQ + k0 + ac);
            float mr = ms[r];
            float4 p;
            p.x = __expf(v.x - mr); p.y = __expf(v.y - mr);
            p.z = __expf(v.z - mr); p.w = __expf(v.w - mr);
            *(float4*)(As + r * 36 + ac) = p;
        }
#pragma unroll
        for (int it = 0; it < 2; it++) {
            int d = br + it * 16;
            *(float4*)(Bs + d * 68 + bc) = *(const float4*)(V + (size_t)(k0 + d) * HDIM + bc);
        }
        __syncthreads();
#pragma unroll
        for (int d = 0; d < 32; d++) {
            float a[8], bb[4];
#pragma unroll
            for (int i = 0; i < 8; i++) a[i]  = As[(tm + i * 16) * 36 + d];
#pragma unroll
            for (int j = 0; j < 4; j++) bb[j] = Bs[d * 68 + tn + j * 16];
#pragma unroll
            for (int i = 0; i < 8; i++)
#pragma unroll
                for (int j = 0; j < 4; j++) acc[i][j] += a[i] * bb[j];
        }
        __syncthreads();
    }

#pragma unroll
    for (int i = 0; i < 8; i++) {
        int m = m0 + tm + i * 16;
        float inv = g_rowinvl[(size_t)z * SEQ + m];
#pragma unroll
        for (int j = 0; j < 4; j++)
            g_obuf[((size_t)(b * HEADS + h) * SEQ + m) * HDIM + tn + j * 16] = acc[i][j] * inv;
    }
}

// ---------------------------------------------------------------------------
// Pass 5: out(8192 x 512) = Concat(8192 x 512) * head_kernel(512 x 512)
// Concat[m][e] (e = h*64+k) gathered from g_obuf[(b*8+h)][s][k].
// ---------------------------------------------------------------------------
__global__ __launch_bounds__(256) void out_gemm(const float* __restrict__ Hk,
                                                float* __restrict__ Out)
{
    __shared__ float As[128 * 36];
    __shared__ float Bs[32 * 132];

    const int tid = threadIdx.x;
    const int m0 = blockIdx.y * 128;
    const int c0 = blockIdx.x * 128;
    const int tm = tid >> 4, tn = tid & 15;
    const int ar = tid >> 3, ac = (tid & 7) * 4;
    const int bdl = tid >> 5, bcl = (tid & 31) * 4;

    float acc[8][8];
#pragma unroll
    for (int i = 0; i < 8; i++)
#pragma unroll
        for (int j = 0; j < 8; j++) acc[i][j] = 0.f;

    for (int e0 = 0; e0 < DMODEL; e0 += 32) {
#pragma unroll
        for (int it = 0; it < 4; it++) {
            int r = ar + it * 32;
            int m = m0 + r;
            int bb_ = m >> 11, s = m & (SEQ - 1);
            int e = e0 + ac;
            int hh = e >> 6, k = e & 63;
            *(float4*)(As + r * 36 + ac) =
                *(const float4*)(g_obuf + ((size_t)(bb_ * HEADS + hh) * SEQ + s) * HDIM + k);
        }
#pragma unroll
        for (int it = 0; it < 4; it++) {
            int d = bdl + it * 8;
            int e = e0 + d;
            *(float4*)(Bs + d * 132 + bcl) = *(const float4*)(Hk + (size_t)e * DMODEL + c0 + bcl);
        }
        __syncthreads();
#pragma unroll
        for (int d = 0; d < 32; d++) {
            float a[8], b[8];
#pragma unroll
            for (int i = 0; i < 8; i++) a[i] = As[(tm + i * 16) * 36 + d];
#pragma unroll
            for (int j = 0; j < 8; j++) b[j] = Bs[d * 132 + tn + j * 16];
#pragma unroll
            for (int i = 0; i < 8; i++)
#pragma unroll
                for (int j = 0; j < 8; j++) acc[i][j] += a[i] * b[j];
        }
        __syncthreads();
    }

#pragma unroll
    for (int i = 0; i < 8; i++) {
        int m = m0 + tm + i * 16;
#pragma unroll
        for (int j = 0; j < 8; j++)
            Out[(size_t)m * DMODEL + c0 + tn + j * 16] = acc[i][j];
    }
}

// ---------------------------------------------------------------------------
extern "C" void kernel_launch(void* const* d_in, const int* in_sizes, int n_in,
                              void* d_out, int out_size)
{
    const float* x  = (const float*)d_in[0];   // (4, 2048, 512)
    const float* w  = (const float*)d_in[1];   // (24, 512, 64)
    const float* hk = (const float*)d_in[2];   // (512, 512)
    float* out = (float*)d_out;                // (4, 2048, 512)

    qkv_gemm<<<dim3(12, 64), 256>>>(x, w);
    qk_gemm<<<dim3(16, 16, 32), 256>>>();
    softmax_stats<<<(BH * SEQ) / 8, 256>>>();
    pv_gemm<<<dim3(16, 32), 256>>>();
    out_gemm<<<dim3(4, 64), 256>>>(hk, out);
}

// round 5
// speedup vs baseline: 1.4430x; 1.4430x over previous
#include <cuda_runtime.h>
#include <cuda_bf16.h>
#include <cstdint>

#define SEQ    2048
#define DM     512
#define HDIM   64
#define HEADS  8
#define BH     32
#define MROWS  8192

// ------------------------------------------------------------------ scratch
__device__ float g_qkv[(size_t)24 * MROWS * HDIM];      // [g=3h+j][m][k] fp32
__device__ float g_vT [(size_t)BH * HDIM * SEQ];        // [z][k][t] fp32
__device__ float g_sbuf[(size_t)BH * SEQ * SEQ];        // scores fp32
__device__ float g_obuf[(size_t)BH * SEQ * HDIM];       // attn out fp32
__device__ float g_rowm[BH * SEQ];
__device__ float g_rowinvl[BH * SEQ];

// ------------------------------------------------------------------ helpers
__device__ __forceinline__ uint32_t smem_u32(const void* p) {
    uint32_t a;
    asm("{ .reg .u64 t; cvta.to.shared.u64 t, %1; cvt.u32.u64 %0, t; }"
        : "=r"(a) : "l"(p));
    return a;
}
#define SWZ(o) ((o) ^ (((o) >> 3) & 0x70))

// bf16 hi/lo split + pack
__device__ __forceinline__ void split2(float a, float b, uint32_t& hi, uint32_t& lo) {
    __nv_bfloat162 h = __floats2bfloat162_rn(a, b);
    float ra = a - __bfloat162float(h.x);
    float rb = b - __bfloat162float(h.y);
    __nv_bfloat162 l = __floats2bfloat162_rn(ra, rb);
    hi = *(uint32_t*)&h;
    lo = *(uint32_t*)&l;
}
__device__ __forceinline__ void pack8(float4 u, float4 w, uint4& hi, uint4& lo) {
    split2(u.x, u.y, hi.x, lo.x);
    split2(u.z, u.w, hi.y, lo.y);
    split2(w.x, w.y, hi.z, lo.z);
    split2(w.z, w.w, hi.w, lo.w);
}

// SMEM: 4 buffers of 128 rows x 128 bytes (64 bf16), SW128 swizzled
#define SOFF_A_HI 0
#define SOFF_A_LO 16384
#define SOFF_B_HI 32768
#define SOFF_B_LO 49152
#define SMEM_BYTES 65536

#define LDSM4(d0, d1, d2, d3, a) \
    asm volatile("ldmatrix.sync.aligned.m8n8.x4.shared.b16 {%0,%1,%2,%3}, [%4];" \
                 : "=r"(d0), "=r"(d1), "=r"(d2), "=r"(d3) : "r"(a))

#define MMA(c, a, b0_, b1_) \
    asm volatile("mma.sync.aligned.m16n8k16.row.col.f32.bf16.bf16.f32 " \
                 "{%0,%1,%2,%3}, {%4,%5,%6,%7}, {%8,%9}, {%0,%1,%2,%3};" \
                 : "+f"((c)[0]), "+f"((c)[1]), "+f"((c)[2]), "+f"((c)[3]) \
                 : "r"((a)[0]), "r"((a)[1]), "r"((a)[2]), "r"((a)[3]), \
                   "r"(b0_), "r"(b1_))

// 3-term split MMA over a staged 128x128 tile (K chunk = 64). Warp layout 4x2:
// warp_m = wid&3 (32 rows), warp_n = wid>>2 (64 cols). acc[2(mt)][8(nt)][4].
__device__ __forceinline__ void compute_128x128(uint32_t sb, int lane,
                                                int warp_m, int warp_n,
                                                float acc[2][8][4])
{
    const int arow = warp_m * 32 + (lane & 15);
    const int acb  = (lane >> 4) * 16;
    const int brow = warp_n * 64 + (lane & 7) + ((lane >> 4) << 3);
    const int bcb  = ((lane >> 3) & 1) * 16;
#pragma unroll
    for (int t = 0; t < 3; t++) {
        uint32_t ab = sb + ((t == 2) ? SOFF_A_LO : SOFF_A_HI);
        uint32_t bb = sb + ((t == 1) ? SOFF_B_LO : SOFF_B_HI);
#pragma unroll
        for (int ks = 0; ks < 4; ks++) {
            const int kb = ks * 32;
            uint32_t a0[4], a1[4];
            LDSM4(a0[0], a0[1], a0[2], a0[3], ab + SWZ(arow * 128 + kb + acb));
            LDSM4(a1[0], a1[1], a1[2], a1[3], ab + SWZ((arow + 16) * 128 + kb + acb));
#pragma unroll
            for (int np = 0; np < 4; np++) {
                uint32_t b[4];
                LDSM4(b[0], b[1], b[2], b[3],
                      bb + SWZ((brow + np * 16) * 128 + kb + bcb));
                MMA(acc[0][np * 2],     a0, b[0], b[1]);
                MMA(acc[0][np * 2 + 1], a0, b[2], b[3]);
                MMA(acc[1][np * 2],     a1, b[0], b[1]);
                MMA(acc[1][np * 2 + 1], a1, b[2], b[3]);
            }
        }
    }
}

// 3-term split MMA over staged 128x64 tile (K chunk = 64). Warp layout 8x1:
// warp wid owns 16 rows, all 64 cols. acc[8(nt)][4].
__device__ __forceinline__ void compute_128x64(uint32_t sb, int lane, int wid,
                                               float acc[8][4])
{
    const int arow = wid * 16 + (lane & 15);
    const int acb  = (lane >> 4) * 16;
    const int brow = (lane & 7) + ((lane >> 4) << 3);
    const int bcb  = ((lane >> 3) & 1) * 16;
#pragma unroll
    for (int t = 0; t < 3; t++) {
        uint32_t ab = sb + ((t == 2) ? SOFF_A_LO : SOFF_A_HI);
        uint32_t bb = sb + ((t == 1) ? SOFF_B_LO : SOFF_B_HI);
#pragma unroll
        for (int ks = 0; ks < 4; ks++) {
            const int kb = ks * 32;
            uint32_t a0[4];
            LDSM4(a0[0], a0[1], a0[2], a0[3], ab + SWZ(arow * 128 + kb + acb));
#pragma unroll
            for (int np = 0; np < 4; np++) {
                uint32_t b[4];
                LDSM4(b[0], b[1], b[2], b[3],
                      bb + SWZ((brow + np * 16) * 128 + kb + bcb));
                MMA(acc[np * 2],     a0, b[0], b[1]);
                MMA(acc[np * 2 + 1], a0, b[2], b[3]);
            }
        }
    }
}

// ---------------------------------------------------------------------------
// Pass 1: QKV projection.  grid (12, 64), 256 thr, 8 chunks of K=64.
// ---------------------------------------------------------------------------
__global__ __launch_bounds__(256) void qkv_mma(const float* __restrict__ X,
                                               const float* __restrict__ W)
{
    extern __shared__ char smem[];
    uint32_t sb = smem_u32(smem);
    const int tid = threadIdx.x, wid = tid >> 5, lane = tid & 31;
    const int m0 = blockIdx.y * 128, c0 = blockIdx.x * 128;
    const int g0 = c0 >> 6;
    const int r = tid >> 1, half = (tid & 1) * 32;

    float acc[2][8][4];
#pragma unroll
    for (int i = 0; i < 2; i++)
#pragma unroll
        for (int j = 0; j < 8; j++)
#pragma unroll
            for (int q = 0; q < 4; q++) acc[i][j][q] = 0.f;

    for (int chunk = 0; chunk < 8; chunk++) {
        const int d0 = chunk * 64;
        // A: X rows
        const float* xa = X + (size_t)(m0 + r) * DM + d0 + half;
#pragma unroll
        for (int g = 0; g < 4; g++) {
            float4 u = *(const float4*)(xa + g * 8);
            float4 w = *(const float4*)(xa + g * 8 + 4);
            uint4 hi, lo; pack8(u, w, hi, lo);
            int off = SWZ(r * 128 + (half + g * 8) * 2);
            *(uint4*)(smem + SOFF_A_HI + off) = hi;
            *(uint4*)(smem + SOFF_A_LO + off) = lo;
        }
        // B: row c = output col, elems = d (strided gather from W)
        const float* wb = W + (size_t)(g0 + r / 64) * (DM * HDIM)
                        + (size_t)(d0 + half) * HDIM + (r & 63);
#pragma unroll
        for (int dg = 0; dg < 4; dg++) {
            float v[8];
#pragma unroll
            for (int e = 0; e < 8; e++) v[e] = wb[(size_t)(dg * 8 + e) * HDIM];
            uint4 hi, lo;
            pack8(make_float4(v[0], v[1], v[2], v[3]),
                  make_float4(v[4], v[5], v[6], v[7]), hi, lo);
            int off = SWZ(r * 128 + (half + dg * 8) * 2);
            *(uint4*)(smem + SOFF_B_HI + off) = hi;
            *(uint4*)(smem + SOFF_B_LO + off) = lo;
        }
        __syncthreads();
        compute_128x128(sb, lane, wid & 3, wid >> 2, acc);
        __syncthreads();
    }

    const int warp_m = wid & 3, warp_n = wid >> 2;
#pragma unroll
    for (int mt = 0; mt < 2; mt++)
#pragma unroll
        for (int h = 0; h < 2; h++) {
            int m = m0 + warp_m * 32 + mt * 16 + (lane >> 2) + h * 8;
            int bidx = m >> 11, s = m & (SEQ - 1);
#pragma unroll
            for (int nt = 0; nt < 8; nt++) {
                int C = c0 + warp_n * 64 + nt * 8 + (lane & 3) * 2;
                int g = C >> 6, kk = C & 63;
                float v0 = acc[mt][nt][h * 2], v1 = acc[mt][nt][h * 2 + 1];
                *(float2*)&g_qkv[((size_t)g * MROWS + m) * HDIM + kk] =
                    make_float2(v0, v1);
                if (g % 3 == 2) {
                    size_t vb = ((size_t)(bidx * HEADS + g / 3) * HDIM + kk) * SEQ + s;
                    g_vT[vb] = v0;
                    g_vT[vb + SEQ] = v1;
                }
            }
        }
}

// ---------------------------------------------------------------------------
// Pass 2: S = Q K^T / 8.  grid (16, 16, 32), 256 thr, single chunk (K=64).
// ---------------------------------------------------------------------------
__global__ __launch_bounds__(256) void qk_mma()
{
    extern __shared__ char smem[];
    uint32_t sb = smem_u32(smem);
    const int tid = threadIdx.x, wid = tid >> 5, lane = tid & 31;
    const int z = blockIdx.z, b = z >> 3, h = z & 7;
    const int m0 = blockIdx.y * 128, n0 = blockIdx.x * 128;
    const int r = tid >> 1, half = (tid & 1) * 32;

    const float* qa = g_qkv + ((size_t)(3 * h)     * MROWS + (size_t)b * SEQ + m0 + r) * HDIM + half;
    const float* ka = g_qkv + ((size_t)(3 * h + 1) * MROWS + (size_t)b * SEQ + n0 + r) * HDIM + half;
#pragma unroll
    for (int g = 0; g < 4; g++) {
        int off = SWZ(r * 128 + (half + g * 8) * 2);
        float4 u = *(const float4*)(qa + g * 8);
        float4 w = *(const float4*)(qa + g * 8 + 4);
        uint4 hi, lo; pack8(u, w, hi, lo);
        *(uint4*)(smem + SOFF_A_HI + off) = hi;
        *(uint4*)(smem + SOFF_A_LO + off) = lo;
        u = *(const float4*)(ka + g * 8);
        w = *(const float4*)(ka + g * 8 + 4);
        pack8(u, w, hi, lo);
        *(uint4*)(smem + SOFF_B_HI + off) = hi;
        *(uint4*)(smem + SOFF_B_LO + off) = lo;
    }
    __syncthreads();

    float acc[2][8][4];
#pragma unroll
    for (int i = 0; i < 2; i++)
#pragma unroll
        for (int j = 0; j < 8; j++)
#pragma unroll
            for (int q = 0; q < 4; q++) acc[i][j][q] = 0.f;

    compute_128x128(sb, lane, wid & 3, wid >> 2, acc);

    const int warp_m = wid & 3, warp_n = wid >> 2;
    float* Sp = g_sbuf + (size_t)z * SEQ * SEQ;
#pragma unroll
    for (int mt = 0; mt < 2; mt++)
#pragma unroll
        for (int h2 = 0; h2 < 2; h2++) {
            int m = m0 + warp_m * 32 + mt * 16 + (lane >> 2) + h2 * 8;
#pragma unroll
            for (int nt = 0; nt < 8; nt++) {
                int n = n0 + warp_n * 64 + nt * 8 + (lane & 3) * 2;
                *(float2*)&Sp[(size_t)m * SEQ + n] =
                    make_float2(acc[mt][nt][h2 * 2] * 0.125f,
                                acc[mt][nt][h2 * 2 + 1] * 0.125f);
            }
        }
}

// ---------------------------------------------------------------------------
// Pass 3: softmax stats (rowmax, 1/sum)
// ---------------------------------------------------------------------------
__global__ __launch_bounds__(256) void softmax_stats()
{
    const int r = blockIdx.x * 8 + (threadIdx.x >> 5);
    const int lane = threadIdx.x & 31;
    const float4* row4 = (const float4*)(g_sbuf + (size_t)r * SEQ);

    float mx = -1e30f;
    for (int j = lane; j < SEQ / 4; j += 32) {
        float4 v = row4[j];
        mx = fmaxf(mx, fmaxf(fmaxf(v.x, v.y), fmaxf(v.z, v.w)));
    }
#pragma unroll
    for (int o = 16; o; o >>= 1) mx = fmaxf(mx, __shfl_xor_sync(0xffffffffu, mx, o));

    float s = 0.f;
    for (int j = lane; j < SEQ / 4; j += 32) {
        float4 v = row4[j];
        s += __expf(v.x - mx) + __expf(v.y - mx) + __expf(v.z - mx) + __expf(v.w - mx);
    }
#pragma unroll
    for (int o = 16; o; o >>= 1) s += __shfl_xor_sync(0xffffffffu, s, o);

    if (lane == 0) {
        g_rowm[r] = mx;
        g_rowinvl[r] = 1.f / s;
    }
}

// ---------------------------------------------------------------------------
// Pass 4: O = softmax(S) V.  grid (16, 32), 256 thr, 32 chunks of K=64.
// ---------------------------------------------------------------------------
__global__ __launch_bounds__(256) void pv_mma()
{
    extern __shared__ char smem[];
    uint32_t sb = smem_u32(smem);
    const int tid = threadIdx.x, wid = tid >> 5, lane = tid & 31;
    const int z = blockIdx.y;
    const int m0 = blockIdx.x * 128;
    const int ra = tid >> 1, halfa = (tid & 1) * 32;     // A staging: 2 thr/row
    const int rb = tid >> 2, qb = (tid & 3) * 16;        // B staging: 4 thr/row

    const float mr = g_rowm[(size_t)z * SEQ + m0 + ra];
    const float* Sp = g_sbuf + (size_t)z * SEQ * SEQ + (size_t)(m0 + ra) * SEQ;
    const float* Vt = g_vT + ((size_t)z * HDIM + rb) * SEQ;

    float acc[8][4];
#pragma unroll
    for (int j = 0; j < 8; j++)
#pragma unroll
        for (int q = 0; q < 4; q++) acc[j][q] = 0.f;

    for (int chunk = 0; chunk < 32; chunk++) {
        const int k0 = chunk * 64;
#pragma unroll
        for (int g = 0; g < 4; g++) {
            float4 u = *(const float4*)(Sp + k0 + halfa + g * 8);
            float4 w = *(const float4*)(Sp + k0 + halfa + g * 8 + 4);
            u.x = __expf(u.x - mr); u.y = __expf(u.y - mr);
            u.z = __expf(u.z - mr); u.w = __expf(u.w - mr);
            w.x = __expf(w.x - mr); w.y = __expf(w.y - mr);
            w.z = __expf(w.z - mr); w.w = __expf(w.w - mr);
            uint4 hi, lo; pack8(u, w, hi, lo);
            int off = SWZ(ra * 128 + (halfa + g * 8) * 2);
            *(uint4*)(smem + SOFF_A_HI + off) = hi;
            *(uint4*)(smem + SOFF_A_LO + off) = lo;
        }
#pragma unroll
        for (int g = 0; g < 2; g++) {
            float4 u = *(const float4*)(Vt + k0 + qb + g * 8);
            float4 w = *(const float4*)(Vt + k0 + qb + g * 8 + 4);
            uint4 hi, lo; pack8(u, w, hi, lo);
            int off = SWZ(rb * 128 + (qb + g * 8) * 2);
            *(uint4*)(smem + SOFF_B_HI + off) = hi;
            *(uint4*)(smem + SOFF_B_LO + off) = lo;
        }
        __syncthreads();
        compute_128x64(sb, lane, wid, acc);
        __syncthreads();
    }

#pragma unroll
    for (int h2 = 0; h2 < 2; h2++) {
        int m = m0 + wid * 16 + (lane >> 2) + h2 * 8;
        float inv = g_rowinvl[(size_t)z * SEQ + m];
        float* op = g_obuf + ((size_t)z * SEQ + m) * HDIM;
#pragma unroll
        for (int nt = 0; nt < 8; nt++) {
            int c = nt * 8 + (lane & 3) * 2;
            *(float2*)&op[c] = make_float2(acc[nt][h2 * 2] * inv,
                                           acc[nt][h2 * 2 + 1] * inv);
        }
    }
}

// ---------------------------------------------------------------------------
// Pass 5: output projection.  grid (4, 64), 256 thr, 8 chunks of K=64.
// ---------------------------------------------------------------------------
__global__ __launch_bounds__(256) void out_mma(const float* __restrict__ Hk,
                                               float* __restrict__ Out)
{
    extern __shared__ char smem[];
    uint32_t sb = smem_u32(smem);
    const int tid = threadIdx.x, wid = tid >> 5, lane = tid & 31;
    const int m0 = blockIdx.y * 128, c0 = blockIdx.x * 128;
    const int r = tid >> 1, half = (tid & 1) * 32;
    const int m = m0 + r, b = m >> 11, s = m & (SEQ - 1);

    float acc[2][8][4];
#pragma unroll
    for (int i = 0; i < 2; i++)
#pragma unroll
        for (int j = 0; j < 8; j++)
#pragma unroll
            for (int q = 0; q < 4; q++) acc[i][j][q] = 0.f;

    for (int chunk = 0; chunk < 8; chunk++) {
        const int e0 = chunk * 64;
        // A: concat rows — head `chunk`, elems contiguous
        const float* oa = g_obuf + ((size_t)(b * HEADS + chunk) * SEQ + s) * HDIM + half;
#pragma unroll
        for (int g = 0; g < 4; g++) {
            float4 u = *(const float4*)(oa + g * 8);
            float4 w = *(const float4*)(oa + g * 8 + 4);
            uint4 hi, lo; pack8(u, w, hi, lo);
            int off = SWZ(r * 128 + (half + g * 8) * 2);
            *(uint4*)(smem + SOFF_A_HI + off) = hi;
            *(uint4*)(smem + SOFF_A_LO + off) = lo;
        }
        // B: row c = output col, elems = e (strided gather from Hk)
        const float* hp = Hk + (size_t)(e0 + half) * DM + c0 + r;
#pragma unroll
        for (int dg = 0; dg < 4; dg++) {
            float v[8];
#pragma unroll
            for (int e = 0; e < 8; e++) v[e] = hp[(size_t)(dg * 8 + e) * DM];
            uint4 hi, lo;
            pack8(make_float4(v[0], v[1], v[2], v[3]),
                  make_float4(v[4], v[5], v[6], v[7]), hi, lo);
            int off = SWZ(r * 128 + (half + dg * 8) * 2);
            *(uint4*)(smem + SOFF_B_HI + off) = hi;
            *(uint4*)(smem + SOFF_B_LO + off) = lo;
        }
        __syncthreads();
        compute_128x128(sb, lane, wid & 3, wid >> 2, acc);
        __syncthreads();
    }

    const int warp_m = wid & 3, warp_n = wid >> 2;
#pragma unroll
    for (int mt = 0; mt < 2; mt++)
#pragma unroll
        for (int h2 = 0; h2 < 2; h2++) {
            int mm = m0 + warp_m * 32 + mt * 16 + (lane >> 2) + h2 * 8;
#pragma unroll
            for (int nt = 0; nt < 8; nt++) {
                int c = c0 + warp_n * 64 + nt * 8 + (lane & 3) * 2;
                *(float2*)&Out[(size_t)mm * DM + c] =
                    make_float2(acc[mt][nt][h2 * 2], acc[mt][nt][h2 * 2 + 1]);
            }
        }
}

// ---------------------------------------------------------------------------
extern "C" void kernel_launch(void* const* d_in, const int* in_sizes, int n_in,
                              void* d_out, int out_size)
{
    const float* x  = (const float*)d_in[0];
    const float* w  = (const float*)d_in[1];
    const float* hk = (const float*)d_in[2];
    float* out = (float*)d_out;

    cudaFuncSetAttribute(qkv_mma, cudaFuncAttributeMaxDynamicSharedMemorySize, SMEM_BYTES);
    cudaFuncSetAttribute(qk_mma,  cudaFuncAttributeMaxDynamicSharedMemorySize, SMEM_BYTES);
    cudaFuncSetAttribute(pv_mma,  cudaFuncAttributeMaxDynamicSharedMemorySize, SMEM_BYTES);
    cudaFuncSetAttribute(out_mma, cudaFuncAttributeMaxDynamicSharedMemorySize, SMEM_BYTES);

    qkv_mma<<<dim3(12, 64), 256, SMEM_BYTES>>>(x, w);
    qk_mma<<<dim3(16, 16, 32), 256, SMEM_BYTES>>>();
    softmax_stats<<<(BH * SEQ) / 8, 256>>>();
    pv_mma<<<dim3(16, 32), 256, SMEM_BYTES>>>();
    out_mma<<<dim3(4, 64), 256, SMEM_BYTES>>>(hk, out);
}

// round 7
// speedup vs baseline: 2.1445x; 1.4862x over previous
#include <cuda_runtime.h>
#include <cuda_bf16.h>
#include <cstdint>

#define SEQ    2048
#define DM     512
#define HDIM   64
#define HEADS  8
#define BH     32
#define MROWS  8192

// ------------------------------------------------------------------ scratch
__device__ float g_qkv[(size_t)24 * MROWS * HDIM];      // [g=3h+j][m][k] fp32
__device__ float g_vT [(size_t)BH * HDIM * SEQ];        // [z][k][t] fp32
__device__ float g_obuf[(size_t)BH * SEQ * HDIM];       // attn out fp32

// ------------------------------------------------------------------ helpers
__device__ __forceinline__ uint32_t smem_u32(const void* p) {
    uint32_t a;
    asm("{ .reg .u64 t; cvta.to.shared.u64 t, %1; cvt.u32.u64 %0, t; }"
        : "=r"(a) : "l"(p));
    return a;
}
#define SWZ(o) ((o) ^ (((o) >> 3) & 0x70))

__device__ __forceinline__ void split2(float a, float b, uint32_t& hi, uint32_t& lo) {
    __nv_bfloat162 h = __floats2bfloat162_rn(a, b);
    float ra = a - __bfloat162float(h.x);
    float rb = b - __bfloat162float(h.y);
    __nv_bfloat162 l = __floats2bfloat162_rn(ra, rb);
    hi = *(uint32_t*)&h;
    lo = *(uint32_t*)&l;
}
__device__ __forceinline__ void pack8(float4 u, float4 w, uint4& hi, uint4& lo) {
    split2(u.x, u.y, hi.x, lo.x);
    split2(u.z, u.w, hi.y, lo.y);
    split2(w.x, w.y, hi.z, lo.z);
    split2(w.z, w.w, hi.w, lo.w);
}

// SMEM buffer offsets (GEMM kernels: A/B 128x128B each; FA: Q=A, K=B)
#define SOFF_A_HI 0
#define SOFF_A_LO 16384
#define SOFF_B_HI 32768
#define SOFF_B_LO 49152
#define SMEM_BYTES 65536
// FA extras: V sub-tiles (2 subs x 64 rows x 128B, hi then lo)
#define SOFF_V_HI 65536
#define SOFF_V_LO (65536 + 16384)
#define SMEM_BYTES_FA (65536 + 32768)
// FA merge scratch (reuses A region after last iteration)
#define SOFF_OPART 0          // 128 x 64 fp32 = 32KB
#define SOFF_MPART 32768      // 128 fp32
#define SOFF_LPART 33280      // 128 fp32

#define LDSM4(d0, d1, d2, d3, a) \
    asm volatile("ldmatrix.sync.aligned.m8n8.x4.shared.b16 {%0,%1,%2,%3}, [%4];" \
                 : "=r"(d0), "=r"(d1), "=r"(d2), "=r"(d3) : "r"(a))

#define MMA(c, a, b0_, b1_) \
    asm volatile("mma.sync.aligned.m16n8k16.row.col.f32.bf16.bf16.f32 " \
                 "{%0,%1,%2,%3}, {%4,%5,%6,%7}, {%8,%9}, {%0,%1,%2,%3};" \
                 : "+f"((c)[0]), "+f"((c)[1]), "+f"((c)[2]), "+f"((c)[3]) \
                 : "r"((a)[0]), "r"((a)[1]), "r"((a)[2]), "r"((a)[3]), \
                   "r"(b0_), "r"(b1_))

// 3-term split MMA over staged 128x128 tiles (K chunk = 64). Warp layout 4x2.
__device__ __forceinline__ void compute_128x128(uint32_t sb, int lane,
                                                int warp_m, int warp_n,
                                                float acc[2][8][4])
{
    const int arow = warp_m * 32 + (lane & 15);
    const int acb  = (lane >> 4) * 16;
    const int brow = warp_n * 64 + (lane & 7) + ((lane >> 4) << 3);
    const int bcb  = ((lane >> 3) & 1) * 16;
#pragma unroll
    for (int t = 0; t < 3; t++) {
        uint32_t ab = sb + ((t == 2) ? SOFF_A_LO : SOFF_A_HI);
        uint32_t bb = sb + ((t == 1) ? SOFF_B_LO : SOFF_B_HI);
#pragma unroll
        for (int ks = 0; ks < 4; ks++) {
            const int kb = ks * 32;
            uint32_t a0[4], a1[4];
            LDSM4(a0[0], a0[1], a0[2], a0[3], ab + SWZ(arow * 128 + kb + acb));
            LDSM4(a1[0], a1[1], a1[2], a1[3], ab + SWZ((arow + 16) * 128 + kb + acb));
#pragma unroll
            for (int np = 0; np < 4; np++) {
                uint32_t b[4];
                LDSM4(b[0], b[1], b[2], b[3],
                      bb + SWZ((brow + np * 16) * 128 + kb + bcb));
                MMA(acc[0][np * 2],     a0, b[0], b[1]);
                MMA(acc[0][np * 2 + 1], a0, b[2], b[3]);
                MMA(acc[1][np * 2],     a1, b[0], b[1]);
                MMA(acc[1][np * 2 + 1], a1, b[2], b[3]);
            }
        }
    }
}

// ---------------------------------------------------------------------------
// Pass 1: QKV projection.  grid (12, 64), 256 thr, 8 chunks of K=64.
// ---------------------------------------------------------------------------
__global__ __launch_bounds__(256) void qkv_mma(const float* __restrict__ X,
                                               const float* __restrict__ W)
{
    extern __shared__ char smem[];
    uint32_t sb = smem_u32(smem);
    const int tid = threadIdx.x, wid = tid >> 5, lane = tid & 31;
    const int m0 = blockIdx.y * 128, c0 = blockIdx.x * 128;
    const int g0 = c0 >> 6;
    const int r = tid >> 1, half = (tid & 1) * 32;

    float acc[2][8][4];
#pragma unroll
    for (int i = 0; i < 2; i++)
#pragma unroll
        for (int j = 0; j < 8; j++)
#pragma unroll
            for (int q = 0; q < 4; q++) acc[i][j][q] = 0.f;

    for (int chunk = 0; chunk < 8; chunk++) {
        const int d0 = chunk * 64;
        const float* xa = X + (size_t)(m0 + r) * DM + d0 + half;
#pragma unroll
        for (int g = 0; g < 4; g++) {
            float4 u = *(const float4*)(xa + g * 8);
            float4 w = *(const float4*)(xa + g * 8 + 4);
            uint4 hi, lo; pack8(u, w, hi, lo);
            int off = SWZ(r * 128 + (half + g * 8) * 2);
            *(uint4*)(smem + SOFF_A_HI + off) = hi;
            *(uint4*)(smem + SOFF_A_LO + off) = lo;
        }
        const float* wb = W + (size_t)(g0 + r / 64) * (DM * HDIM)
                        + (size_t)(d0 + half) * HDIM + (r & 63);
#pragma unroll
        for (int dg = 0; dg < 4; dg++) {
            float v[8];
#pragma unroll
            for (int e = 0; e < 8; e++) v[e] = wb[(size_t)(dg * 8 + e) * HDIM];
            uint4 hi, lo;
            pack8(make_float4(v[0], v[1], v[2], v[3]),
                  make_float4(v[4], v[5], v[6], v[7]), hi, lo);
            int off = SWZ(r * 128 + (half + dg * 8) * 2);
            *(uint4*)(smem + SOFF_B_HI + off) = hi;
            *(uint4*)(smem + SOFF_B_LO + off) = lo;
        }
        __syncthreads();
        compute_128x128(sb, lane, wid & 3, wid >> 2, acc);
        __syncthreads();
    }

    const int warp_m = wid & 3, warp_n = wid >> 2;
#pragma unroll
    for (int mt = 0; mt < 2; mt++)
#pragma unroll
        for (int h = 0; h < 2; h++) {
            int m = m0 + warp_m * 32 + mt * 16 + (lane >> 2) + h * 8;
            int bidx = m >> 11, s = m & (SEQ - 1);
#pragma unroll
            for (int nt = 0; nt < 8; nt++) {
                int C = c0 + warp_n * 64 + nt * 8 + (lane & 3) * 2;
                int g = C >> 6, kk = C & 63;
                float v0 = acc[mt][nt][h * 2], v1 = acc[mt][nt][h * 2 + 1];
                *(float2*)&g_qkv[((size_t)g * MROWS + m) * HDIM + kk] =
                    make_float2(v0, v1);
                if (g % 3 == 2) {
                    size_t vb = ((size_t)(bidx * HEADS + g / 3) * HDIM + kk) * SEQ + s;
                    g_vT[vb] = v0;
                    g_vT[vb + SEQ] = v1;
                }
            }
        }
}

// ---------------------------------------------------------------------------
// Pass 2: fused flash attention.  grid (16, 32), 256 thr, 16 k-tiles of 128.
// Q (x 1/8) resident in A bufs; K tile in B bufs; V tile (from g_vT) in V bufs.
// Per-warp online softmax over its 64-col slice; final split-k merge in SMEM.
// ---------------------------------------------------------------------------
__global__ __launch_bounds__(256) void fa_mma()
{
    extern __shared__ char smem[];
    uint32_t sb = smem_u32(smem);
    const int tid = threadIdx.x, wid = tid >> 5, lane = tid & 31;
    const int z = blockIdx.y, b = z >> 3, h = z & 7;
    const int m0 = blockIdx.x * 128;
    const int warp_m = wid & 3, warp_kn = wid >> 2;
    const int r = tid >> 1, half = (tid & 1) * 32;
    const int rb = tid >> 2, qb = (tid & 3) * 16;

    // ---- stage Q (scaled by 1/8), resident for whole kernel
    {
        const float* qa = g_qkv + ((size_t)(3 * h) * MROWS + (size_t)b * SEQ + m0 + r) * HDIM + half;
#pragma unroll
        for (int g = 0; g < 4; g++) {
            float4 u = *(const float4*)(qa + g * 8);
            float4 w = *(const float4*)(qa + g * 8 + 4);
            u.x *= 0.125f; u.y *= 0.125f; u.z *= 0.125f; u.w *= 0.125f;
            w.x *= 0.125f; w.y *= 0.125f; w.z *= 0.125f; w.w *= 0.125f;
            uint4 hi, lo; pack8(u, w, hi, lo);
            int off = SWZ(r * 128 + (half + g * 8) * 2);
            *(uint4*)(smem + SOFF_A_HI + off) = hi;
            *(uint4*)(smem + SOFF_A_LO + off) = lo;
        }
    }

    float Oacc[2][8][4];
#pragma unroll
    for (int i = 0; i < 2; i++)
#pragma unroll
        for (int j = 0; j < 8; j++)
#pragma unroll
            for (int q = 0; q < 4; q++) Oacc[i][j][q] = 0.f;
    float mrow[2][2] = {{-1e30f, -1e30f}, {-1e30f, -1e30f}};
    float lrow[2][2] = {{0.f, 0.f}, {0.f, 0.f}};

    const float* Kbase = g_qkv + ((size_t)(3 * h + 1) * MROWS + (size_t)b * SEQ) * HDIM;
    const float* Vt = g_vT + ((size_t)z * HDIM + rb) * SEQ;

    const int brow = (lane & 7) + ((lane >> 4) << 3);
    const int bcb  = ((lane >> 3) & 1) * 16;

    for (int kt = 0; kt < 16; kt++) {
        const int t0 = kt * 128;
        // ---- stage K tile (rows t, cols d) into B bufs
        const float* ka = Kbase + (size_t)(t0 + r) * HDIM + half;
#pragma unroll
        for (int g = 0; g < 4; g++) {
            float4 u = *(const float4*)(ka + g * 8);
            float4 w = *(const float4*)(ka + g * 8 + 4);
            uint4 hi, lo; pack8(u, w, hi, lo);
            int off = SWZ(r * 128 + (half + g * 8) * 2);
            *(uint4*)(smem + SOFF_B_HI + off) = hi;
            *(uint4*)(smem + SOFF_B_LO + off) = lo;
        }
        // ---- stage V tile: 2 sub-buffers of [d 64][t 64]
#pragma unroll
        for (int sub = 0; sub < 2; sub++) {
#pragma unroll
            for (int g = 0; g < 2; g++) {
                float4 u = *(const float4*)(Vt + t0 + sub * 64 + qb + g * 8);
                float4 w = *(const float4*)(Vt + t0 + sub * 64 + qb + g * 8 + 4);
                uint4 hi, lo; pack8(u, w, hi, lo);
                int off = SWZ(rb * 128 + (qb + g * 8) * 2) + sub * 8192;
                *(uint4*)(smem + SOFF_V_HI + off) = hi;
                *(uint4*)(smem + SOFF_V_LO + off) = lo;
            }
        }
        __syncthreads();

        // ---- S = (Q/8) K^T   (split-3)
        float sacc[2][8][4];
#pragma unroll
        for (int i = 0; i < 2; i++)
#pragma unroll
            for (int j = 0; j < 8; j++)
#pragma unroll
                for (int q = 0; q < 4; q++) sacc[i][j][q] = 0.f;
        compute_128x128(sb, lane, warp_m, warp_kn, sacc);

        // ---- online softmax (per warp, its 64 cols), P left in sacc
#pragma unroll
        for (int mt = 0; mt < 2; mt++)
#pragma unroll
            for (int h2 = 0; h2 < 2; h2++) {
                float mx = -1e30f;
#pragma unroll
                for (int nt = 0; nt < 8; nt++)
                    mx = fmaxf(mx, fmaxf(sacc[mt][nt][h2 * 2], sacc[mt][nt][h2 * 2 + 1]));
                mx = fmaxf(mx, __shfl_xor_sync(0xffffffffu, mx, 1));
                mx = fmaxf(mx, __shfl_xor_sync(0xffffffffu, mx, 2));
                float mold = mrow[mt][h2];
                float mnew = fmaxf(mold, mx);
                float alpha = __expf(mold - mnew);
                mrow[mt][h2] = mnew;
                float rsum = 0.f;
#pragma unroll
                for (int nt = 0; nt < 8; nt++) {
                    float p0 = __expf(sacc[mt][nt][h2 * 2] - mnew);
                    float p1 = __expf(sacc[mt][nt][h2 * 2 + 1] - mnew);
                    sacc[mt][nt][h2 * 2] = p0;
                    sacc[mt][nt][h2 * 2 + 1] = p1;
                    rsum += p0 + p1;
                }
                rsum += __shfl_xor_sync(0xffffffffu, rsum, 1);
                rsum += __shfl_xor_sync(0xffffffffu, rsum, 2);
                lrow[mt][h2] = lrow[mt][h2] * alpha + rsum;
#pragma unroll
                for (int nt = 0; nt < 8; nt++) {
                    Oacc[mt][nt][h2 * 2] *= alpha;
                    Oacc[mt][nt][h2 * 2 + 1] *= alpha;
                }
            }

        // ---- O += P V   (P hi/lo from regs; V from this warp's k-half sub-buffer)
        uint32_t vh = sb + SOFF_V_HI + warp_kn * 8192;
        uint32_t vl = sb + SOFF_V_LO + warp_kn * 8192;
#pragma unroll
        for (int ks = 0; ks < 4; ks++) {
            uint32_t pah[2][4], pal[2][4];
#pragma unroll
            for (int mt = 0; mt < 2; mt++) {
                split2(sacc[mt][2 * ks][0],     sacc[mt][2 * ks][1],     pah[mt][0], pal[mt][0]);
                split2(sacc[mt][2 * ks][2],     sacc[mt][2 * ks][3],     pah[mt][1], pal[mt][1]);
                split2(sacc[mt][2 * ks + 1][0], sacc[mt][2 * ks + 1][1], pah[mt][2], pal[mt][2]);
                split2(sacc[mt][2 * ks + 1][2], sacc[mt][2 * ks + 1][3], pah[mt][3], pal[mt][3]);
            }
#pragma unroll
            for (int np = 0; np < 4; np++) {
                uint32_t bh[4], bl[4];
                LDSM4(bh[0], bh[1], bh[2], bh[3],
                      vh + SWZ((brow + np * 16) * 128 + ks * 32 + bcb));
                LDSM4(bl[0], bl[1], bl[2], bl[3],
                      vl + SWZ((brow + np * 16) * 128 + ks * 32 + bcb));
#pragma unroll
                for (int mt = 0; mt < 2; mt++) {
                    MMA(Oacc[mt][np * 2],     pah[mt], bh[0], bh[1]);
                    MMA(Oacc[mt][np * 2 + 1], pah[mt], bh[2], bh[3]);
                    MMA(Oacc[mt][np * 2],     pah[mt], bl[0], bl[1]);
                    MMA(Oacc[mt][np * 2 + 1], pah[mt], bl[2], bl[3]);
                    MMA(Oacc[mt][np * 2],     pal[mt], bh[0], bh[1]);
                    MMA(Oacc[mt][np * 2 + 1], pal[mt], bh[2], bh[3]);
                }
            }
        }
        __syncthreads();   // done with K/V bufs before next stage
    }

    // ---- merge the two k-half partials (warp_kn 0 vs 1), write O
    float* mpart = (float*)(smem + SOFF_MPART);
    float* lpart = (float*)(smem + SOFF_LPART);
    float* Opart = (float*)(smem + SOFF_OPART);

    if (warp_kn == 1) {
#pragma unroll
        for (int mt = 0; mt < 2; mt++)
#pragma unroll
            for (int h2 = 0; h2 < 2; h2++) {
                int row = warp_m * 32 + mt * 16 + h2 * 8 + (lane >> 2);
                if ((lane & 3) == 0) {
                    mpart[row] = mrow[mt][h2];
                    lpart[row] = lrow[mt][h2];
                }
#pragma unroll
                for (int nt = 0; nt < 8; nt++) {
                    int col = nt * 8 + (lane & 3) * 2;
                    *(float2*)&Opart[row * 64 + col] =
                        make_float2(Oacc[mt][nt][h2 * 2], Oacc[mt][nt][h2 * 2 + 1]);
                }
            }
    }
    __syncthreads();
    if (warp_kn == 0) {
#pragma unroll
        for (int mt = 0; mt < 2; mt++)
#pragma unroll
            for (int h2 = 0; h2 < 2; h2++) {
                int row = warp_m * 32 + mt * 16 + h2 * 8 + (lane >> 2);
                float m1 = mpart[row], l1 = lpart[row];
                float m0_ = mrow[mt][h2], l0 = lrow[mt][h2];
                float mf = fmaxf(m0_, m1);
                float a0 = __expf(m0_ - mf), a1 = __expf(m1 - mf);
                float inv = 1.f / (l0 * a0 + l1 * a1);
                float* op = g_obuf + ((size_t)z * SEQ + m0 + row) * HDIM;
#pragma unroll
                for (int nt = 0; nt < 8; nt++) {
                    int col = nt * 8 + (lane & 3) * 2;
                    float2 o1 = *(float2*)&Opart[row * 64 + col];
                    *(float2*)&op[col] = make_float2(
                        (Oacc[mt][nt][h2 * 2]     * a0 + o1.x * a1) * inv,
                        (Oacc[mt][nt][h2 * 2 + 1] * a0 + o1.y * a1) * inv);
                }
            }
    }
}

// ---------------------------------------------------------------------------
// Pass 3: output projection.  grid (4, 64), 256 thr, 8 chunks of K=64.
// ---------------------------------------------------------------------------
__global__ __launch_bounds__(256) void out_mma(const float* __restrict__ Hk,
                                               float* __restrict__ Out)
{
    extern __shared__ char smem[];
    uint32_t sb = smem_u32(smem);
    const int tid = threadIdx.x, wid = tid >> 5, lane = tid & 31;
    const int m0 = blockIdx.y * 128, c0 = blockIdx.x * 128;
    const int r = tid >> 1, half = (tid & 1) * 32;
    const int m = m0 + r, b = m >> 11, s = m & (SEQ - 1);

    float acc[2][8][4];
#pragma unroll
    for (int i = 0; i < 2; i++)
#pragma unroll
        for (int j = 0; j < 8; j++)
#pragma unroll
            for (int q = 0; q < 4; q++) acc[i][j][q] = 0.f;

    for (int chunk = 0; chunk < 8; chunk++) {
        const int e0 = chunk * 64;
        const float* oa = g_obuf + ((size_t)(b * HEADS + chunk) * SEQ + s) * HDIM + half;
#pragma unroll
        for (int g = 0; g < 4; g++) {
            float4 u = *(const float4*)(oa + g * 8);
            float4 w = *(const float4*)(oa + g * 8 + 4);
            uint4 hi, lo; pack8(u, w, hi, lo);
            int off = SWZ(r * 128 + (half + g * 8) * 2);
            *(uint4*)(smem + SOFF_A_HI + off) = hi;
            *(uint4*)(smem + SOFF_A_LO + off) = lo;
        }
        const float* hp = Hk + (size_t)(e0 + half) * DM + c0 + r;
#pragma unroll
        for (int dg = 0; dg < 4; dg++) {
            float v[8];
#pragma unroll
            for (int e = 0; e < 8; e++) v[e] = hp[(size_t)(dg * 8 + e) * DM];
            uint4 hi, lo;
            pack8(make_float4(v[0], v[1], v[2], v[3]),
                  make_float4(v[4], v[5], v[6], v[7]), hi, lo);
            int off = SWZ(r * 128 + (half + dg * 8) * 2);
            *(uint4*)(smem + SOFF_B_HI + off) = hi;
            *(uint4*)(smem + SOFF_B_LO + off) = lo;
        }
        __syncthreads();
        compute_128x128(sb, lane, wid & 3, wid >> 2, acc);
        __syncthreads();
    }

    const int warp_m = wid & 3, warp_n = wid >> 2;
#pragma unroll
    for (int mt = 0; mt < 2; mt++)
#pragma unroll
        for (int h2 = 0; h2 < 2; h2++) {
            int mm = m0 + warp_m * 32 + mt * 16 + (lane >> 2) + h2 * 8;
#pragma unroll
            for (int nt = 0; nt < 8; nt++) {
                int c = c0 + warp_n * 64 + nt * 8 + (lane & 3) * 2;
                *(float2*)&Out[(size_t)mm * DM + c] =
                    make_float2(acc[mt][nt][h2 * 2], acc[mt][nt][h2 * 2 + 1]);
            }
        }
}

// ---------------------------------------------------------------------------
extern "C" void kernel_launch(void* const* d_in, const int* in_sizes, int n_in,
                              void* d_out, int out_size)
{
    const float* x  = (const float*)d_in[0];
    const float* w  = (const float*)d_in[1];
    const float* hk = (const float*)d_in[2];
    float* out = (float*)d_out;

    cudaFuncSetAttribute(qkv_mma, cudaFuncAttributeMaxDynamicSharedMemorySize, SMEM_BYTES);
    cudaFuncSetAttribute(fa_mma,  cudaFuncAttributeMaxDynamicSharedMemorySize, SMEM_BYTES_FA);
    cudaFuncSetAttribute(out_mma, cudaFuncAttributeMaxDynamicSharedMemorySize, SMEM_BYTES);

    qkv_mma<<<dim3(12, 64), 256, SMEM_BYTES>>>(x, w);
    fa_mma<<<dim3(16, 32), 256, SMEM_BYTES_FA>>>();
    out_mma<<<dim3(4, 64), 256, SMEM_BYTES>>>(hk, out);
}

// round 11
// speedup vs baseline: 2.7255x; 1.2709x over previous
#include <cuda_runtime.h>
#include <cuda_bf16.h>
#include <cstdint>

#define SEQ    2048
#define DM     512
#define HDIM   64
#define HEADS  8
#define BH     32
#define MROWS  8192

// ------------------------------------------------------------------ scratch
// Pre-split bf16 hi/lo, pre-swizzled within each 128B row.
// Q/K: [z][s] rows of 64 bf16 (Q pre-scaled by 1/8).
// V:   [z][d] rows of 2048 bf16 along t, in 128B chunks of 64.
__device__ uint4 g_q16hi[(size_t)BH * SEQ * 8];
__device__ uint4 g_q16lo[(size_t)BH * SEQ * 8];
__device__ uint4 g_k16hi[(size_t)BH * SEQ * 8];
__device__ uint4 g_k16lo[(size_t)BH * SEQ * 8];
__device__ uint4 g_v16hi[(size_t)BH * HDIM * 32 * 8];
__device__ uint4 g_v16lo[(size_t)BH * HDIM * 32 * 8];
__device__ float g_obuf[(size_t)BH * SEQ * HDIM];

// ------------------------------------------------------------------ helpers
__device__ __forceinline__ uint32_t smem_u32(const void* p) {
    uint32_t a;
    asm("{ .reg .u64 t; cvta.to.shared.u64 t, %1; cvt.u32.u64 %0, t; }"
        : "=r"(a) : "l"(p));
    return a;
}
#define SWZ(o) ((o) ^ (((o) >> 3) & 0x70))

__device__ __forceinline__ void split2(float a, float b, uint32_t& hi, uint32_t& lo) {
    __nv_bfloat162 h = __floats2bfloat162_rn(a, b);
    float ra = a - __bfloat162float(h.x);
    float rb = b - __bfloat162float(h.y);
    __nv_bfloat162 l = __floats2bfloat162_rn(ra, rb);
    hi = *(uint32_t*)&h;
    lo = *(uint32_t*)&l;
}
__device__ __forceinline__ void pack8(float4 u, float4 w, uint4& hi, uint4& lo) {
    split2(u.x, u.y, hi.x, lo.x);
    split2(u.z, u.w, hi.y, lo.y);
    split2(w.x, w.y, hi.z, lo.z);
    split2(w.z, w.w, hi.w, lo.w);
}

// GEMM-kernel SMEM (qkv / out): 4 buffers of 128 rows x 128B
#define SOFF_A_HI 0
#define SOFF_A_LO 16384
#define SOFF_B_HI 32768
#define SOFF_B_LO 49152
#define SMEM_BYTES 65536

// FA SMEM: Q resident + 2 stages of (K 32K + V 32K)
#define FQ_HI 0
#define FQ_LO 16384
#define FSTG  32768
#define FSTG_SZ 65536
#define FK_HI 0
#define FK_LO 16384
#define FV_HI 32768
#define FV_LO 49152
#define FA_SMEM (32768 + 2 * 65536)     // 163840
#define F_OPART 32768                    // merge scratch aliases stage 0
#define F_MPART (32768 + 32768)
#define F_LPART (32768 + 32768 + 512)

#define LDSM4(d0, d1, d2, d3, a) \
    asm volatile("ldmatrix.sync.aligned.m8n8.x4.shared.b16 {%0,%1,%2,%3}, [%4];" \
                 : "=r"(d0), "=r"(d1), "=r"(d2), "=r"(d3) : "r"(a))

#define MMA(c, a, b0_, b1_) \
    asm volatile("mma.sync.aligned.m16n8k16.row.col.f32.bf16.bf16.f32 " \
                 "{%0,%1,%2,%3}, {%4,%5,%6,%7}, {%8,%9}, {%0,%1,%2,%3};" \
                 : "+f"((c)[0]), "+f"((c)[1]), "+f"((c)[2]), "+f"((c)[3]) \
                 : "r"((a)[0]), "r"((a)[1]), "r"((a)[2]), "r"((a)[3]), \
                   "r"(b0_), "r"(b1_))

#define CP16(sa, gp) asm volatile("cp.async.cg.shared.global [%0], [%1], 16;" \
                                  :: "r"(sa), "l"(gp) : "memory")
#define CPC()  asm volatile("cp.async.commit_group;" ::: "memory")
#define CPW(n) asm volatile("cp.async.wait_group %0;" :: "n"(n) : "memory")

// 3-term split MMA over 128x128 tiles (K chunk = 64). Warp layout 4x2.
__device__ __forceinline__ void compute_tile(uint32_t ah, uint32_t al,
                                             uint32_t bh_, uint32_t bl_,
                                             int lane, int warp_m, int warp_n,
                                             float acc[2][8][4])
{
    const int arow = warp_m * 32 + (lane & 15);
    const int acb  = (lane >> 4) * 16;
    const int brow = warp_n * 64 + (lane & 7) + ((lane >> 4) << 3);
    const int bcb  = ((lane >> 3) & 1) * 16;
#pragma unroll
    for (int t = 0; t < 3; t++) {
        uint32_t ab = (t == 2) ? al : ah;
        uint32_t bb = (t == 1) ? bl_ : bh_;
#pragma unroll
        for (int ks = 0; ks < 4; ks++) {
            const int kb = ks * 32;
            uint32_t a0[4], a1[4];
            LDSM4(a0[0], a0[1], a0[2], a0[3], ab + SWZ(arow * 128 + kb + acb));
            LDSM4(a1[0], a1[1], a1[2], a1[3], ab + SWZ((arow + 16) * 128 + kb + acb));
#pragma unroll
            for (int np = 0; np < 4; np++) {
                uint32_t b[4];
                LDSM4(b[0], b[1], b[2], b[3],
                      bb + SWZ((brow + np * 16) * 128 + kb + bcb));
                MMA(acc[0][np * 2],     a0, b[0], b[1]);
                MMA(acc[0][np * 2 + 1], a0, b[2], b[3]);
                MMA(acc[1][np * 2],     a1, b[0], b[1]);
                MMA(acc[1][np * 2 + 1], a1, b[2], b[3]);
            }
        }
    }
}

// ---------------------------------------------------------------------------
// Pass 1: QKV projection.  grid (12, 64), 256 thr, 8 chunks of K=64.
// Epilogue writes pre-split, pre-swizzled bf16 hi/lo (Q scaled by 1/8).
// ---------------------------------------------------------------------------
__global__ __launch_bounds__(256) void qkv_mma(const float* __restrict__ X,
                                               const float* __restrict__ W)
{
    extern __shared__ char smem[];
    uint32_t sb = smem_u32(smem);
    const int tid = threadIdx.x, wid = tid >> 5, lane = tid & 31;
    const int m0 = blockIdx.y * 128, c0 = blockIdx.x * 128;
    const int g0 = c0 >> 6;
    const int r = tid >> 1, half = (tid & 1) * 32;

    float acc[2][8][4];
#pragma unroll
    for (int i = 0; i < 2; i++)
#pragma unroll
        for (int j = 0; j < 8; j++)
#pragma unroll
            for (int q = 0; q < 4; q++) acc[i][j][q] = 0.f;

    for (int chunk = 0; chunk < 8; chunk++) {
        const int d0 = chunk * 64;
        const float* xa = X + (size_t)(m0 + r) * DM + d0 + half;
#pragma unroll
        for (int g = 0; g < 4; g++) {
            float4 u = *(const float4*)(xa + g * 8);
            float4 w = *(const float4*)(xa + g * 8 + 4);
            uint4 hi, lo; pack8(u, w, hi, lo);
            int off = SWZ(r * 128 + (half + g * 8) * 2);
            *(uint4*)(smem + SOFF_A_HI + off) = hi;
            *(uint4*)(smem + SOFF_A_LO + off) = lo;
        }
        const float* wb = W + (size_t)(g0 + r / 64) * (DM * HDIM)
                        + (size_t)(d0 + half) * HDIM + (r & 63);
#pragma unroll
        for (int dg = 0; dg < 4; dg++) {
            float v[8];
#pragma unroll
            for (int e = 0; e < 8; e++) v[e] = wb[(size_t)(dg * 8 + e) * HDIM];
            uint4 hi, lo;
            pack8(make_float4(v[0], v[1], v[2], v[3]),
                  make_float4(v[4], v[5], v[6], v[7]), hi, lo);
            int off = SWZ(r * 128 + (half + dg * 8) * 2);
            *(uint4*)(smem + SOFF_B_HI + off) = hi;
            *(uint4*)(smem + SOFF_B_LO + off) = lo;
        }
        __syncthreads();
        compute_tile(sb + SOFF_A_HI, sb + SOFF_A_LO, sb + SOFF_B_HI, sb + SOFF_B_LO,
                     lane, wid & 3, wid >> 2, acc);
        __syncthreads();
    }

    const int warp_m = wid & 3, warp_n = wid >> 2;
#pragma unroll
    for (int mt = 0; mt < 2; mt++)
#pragma unroll
        for (int h2 = 0; h2 < 2; h2++) {
            int m = m0 + warp_m * 32 + mt * 16 + (lane >> 2) + h2 * 8;
            int bidx = m >> 11, s = m & (SEQ - 1);
#pragma unroll
            for (int nt = 0; nt < 8; nt++) {
                int C = c0 + warp_n * 64 + nt * 8 + (lane & 3) * 2;
                int g = C >> 6, kk = C & 63;
                int type = g % 3, hd = g / 3;
                int z = bidx * HEADS + hd;
                float v0 = acc[mt][nt][h2 * 2], v1 = acc[mt][nt][h2 * 2 + 1];
                if (type == 0) { v0 *= 0.125f; v1 *= 0.125f; }
                uint32_t hi, lo; split2(v0, v1, hi, lo);
                if (type == 2) {
                    // V^T: value (d=kk, t=s) and (d=kk+1, t=s), 2B each
                    size_t b0 = ((size_t)z * HDIM + kk)     * 4096;
                    size_t b1 = ((size_t)z * HDIM + kk + 1) * 4096;
                    int co = (s >> 6) * 128;
                    int so0 = ((s & 63) * 2) ^ ((kk & 7) << 4);
                    int so1 = ((s & 63) * 2) ^ (((kk + 1) & 7) << 4);
                    ((uint16_t*)g_v16hi)[(b0 + co + so0) >> 1] = (uint16_t)(hi & 0xffff);
                    ((uint16_t*)g_v16hi)[(b1 + co + so1) >> 1] = (uint16_t)(hi >> 16);
                    ((uint16_t*)g_v16lo)[(b0 + co + so0) >> 1] = (uint16_t)(lo & 0xffff);
                    ((uint16_t*)g_v16lo)[(b1 + co + so1) >> 1] = (uint16_t)(lo >> 16);
                } else {
                    size_t rb = ((size_t)z * SEQ + s) * 128;
                    int so = (kk * 2) ^ ((s & 7) << 4);
                    char* ah = (char*)(type ? g_k16hi : g_q16hi);
                    char* al = (char*)(type ? g_k16lo : g_q16lo);
                    *(uint32_t*)(ah + rb + so) = hi;
                    *(uint32_t*)(al + rb + so) = lo;
                }
            }
        }
}

// ---------------------------------------------------------------------------
// FA prefetch: K tile (128 rows x 128B hi+lo) + V tile (2 subs x 64 rows) via cp.async
// ---------------------------------------------------------------------------
__device__ __forceinline__ void fa_prefetch(uint32_t stg, int z, int kt, int tid)
{
    const char* kh = (const char*)g_k16hi + ((size_t)z * SEQ + kt * 128) * 128;
    const char* kl = (const char*)g_k16lo + ((size_t)z * SEQ + kt * 128) * 128;
#pragma unroll
    for (int i = 0; i < 4; i++) {
        int o = (tid + i * 256) * 16;
        CP16(stg + FK_HI + o, kh + o);
        CP16(stg + FK_LO + o, kl + o);
    }
    const char* vh = (const char*)g_v16hi;
    const char* vl = (const char*)g_v16lo;
#pragma unroll
    for (int s2 = 0; s2 < 2; s2++) {
#pragma unroll
        for (int i = 0; i < 2; i++) {
            int j = tid + i * 256;
            int d = j >> 3, off = (j & 7) * 16;
            size_t gb = ((size_t)z * HDIM + d) * 4096 + (size_t)(kt * 2 + s2) * 128 + off;
            CP16(stg + FV_HI + s2 * 8192 + d * 128 + off, vh + gb);
            CP16(stg + FV_LO + s2 * 8192 + d * 128 + off, vl + gb);
        }
    }
}

// ---------------------------------------------------------------------------
// Pass 2: fused flash attention.  grid (16, 32), 256 thr, 16 k-tiles of 128.
// Q resident; K/V double-buffered via cp.async; no conversions in-loop.
// ---------------------------------------------------------------------------
__global__ __launch_bounds__(256) void fa_mma()
{
    extern __shared__ char smem[];
    uint32_t sb = smem_u32(smem);
    const int tid = threadIdx.x, wid = tid >> 5, lane = tid & 31;
    const int z = blockIdx.y;
    const int m0 = blockIdx.x * 128;
    const int warp_m = wid & 3, warp_kn = wid >> 2;

    // ---- Q load (group 0, together with stage-0 K/V)
    {
        const char* qh = (const char*)g_q16hi + ((size_t)z * SEQ + m0) * 128;
        const char* ql = (const char*)g_q16lo + ((size_t)z * SEQ + m0) * 128;
#pragma unroll
        for (int i = 0; i < 4; i++) {
            int o = (tid + i * 256) * 16;
            CP16(sb + FQ_HI + o, qh + o);
            CP16(sb + FQ_LO + o, ql + o);
        }
    }
    fa_prefetch(sb + FSTG, z, 0, tid);
    CPC();

    float Oacc[2][8][4];
#pragma unroll
    for (int i = 0; i < 2; i++)
#pragma unroll
        for (int j = 0; j < 8; j++)
#pragma unroll
            for (int q = 0; q < 4; q++) Oacc[i][j][q] = 0.f;
    float mrow[2][2] = {{-1e30f, -1e30f}, {-1e30f, -1e30f}};
    float lrow[2][2] = {{0.f, 0.f}, {0.f, 0.f}};

    const int brow = (lane & 7) + ((lane >> 4) << 3);
    const int bcb  = ((lane >> 3) & 1) * 16;

    for (int kt = 0; kt < 16; kt++) {
        uint32_t stg = sb + FSTG + (kt & 1) * FSTG_SZ;
        if (kt < 15) {
            fa_prefetch(sb + FSTG + ((kt + 1) & 1) * FSTG_SZ, z, kt + 1, tid);
            CPC();
            CPW(1);
        } else {
            CPW(0);
        }
        __syncthreads();

        // ---- S = (Q/8) K^T (split-3)
        float sacc[2][8][4];
#pragma unroll
        for (int i = 0; i < 2; i++)
#pragma unroll
            for (int j = 0; j < 8; j++)
#pragma unroll
                for (int q = 0; q < 4; q++) sacc[i][j][q] = 0.f;
        compute_tile(sb + FQ_HI, sb + FQ_LO, stg + FK_HI, stg + FK_LO,
                     lane, warp_m, warp_kn, sacc);

        // ---- online softmax (per warp 64-col slice)
#pragma unroll
        for (int mt = 0; mt < 2; mt++)
#pragma unroll
            for (int h2 = 0; h2 < 2; h2++) {
                float mx = -1e30f;
#pragma unroll
                for (int nt = 0; nt < 8; nt++)
                    mx = fmaxf(mx, fmaxf(sacc[mt][nt][h2 * 2], sacc[mt][nt][h2 * 2 + 1]));
                mx = fmaxf(mx, __shfl_xor_sync(0xffffffffu, mx, 1));
                mx = fmaxf(mx, __shfl_xor_sync(0xffffffffu, mx, 2));
                float mold = mrow[mt][h2];
                float mnew = fmaxf(mold, mx);
                float alpha = __expf(mold - mnew);
                mrow[mt][h2] = mnew;
                float rsum = 0.f;
#pragma unroll
                for (int nt = 0; nt < 8; nt++) {
                    float p0 = __expf(sacc[mt][nt][h2 * 2] - mnew);
                    float p1 = __expf(sacc[mt][nt][h2 * 2 + 1] - mnew);
                    sacc[mt][nt][h2 * 2] = p0;
                    sacc[mt][nt][h2 * 2 + 1] = p1;
                    rsum += p0 + p1;
                }
                rsum += __shfl_xor_sync(0xffffffffu, rsum, 1);
                rsum += __shfl_xor_sync(0xffffffffu, rsum, 2);
                lrow[mt][h2] = lrow[mt][h2] * alpha + rsum;
#pragma unroll
                for (int nt = 0; nt < 8; nt++) {
                    Oacc[mt][nt][h2 * 2] *= alpha;
                    Oacc[mt][nt][h2 * 2 + 1] *= alpha;
                }
            }

        // ---- O += P V
        uint32_t vh = stg + FV_HI + warp_kn * 8192;
        uint32_t vl = stg + FV_LO + warp_kn * 8192;
#pragma unroll
        for (int ks = 0; ks < 4; ks++) {
            uint32_t pah[2][4], pal[2][4];
#pragma unroll
            for (int mt = 0; mt < 2; mt++) {
                split2(sacc[mt][2 * ks][0],     sacc[mt][2 * ks][1],     pah[mt][0], pal[mt][0]);
                split2(sacc[mt][2 * ks][2],     sacc[mt][2 * ks][3],     pah[mt][1], pal[mt][1]);
                split2(sacc[mt][2 * ks + 1][0], sacc[mt][2 * ks + 1][1], pah[mt][2], pal[mt][2]);
                split2(sacc[mt][2 * ks + 1][2], sacc[mt][2 * ks + 1][3], pah[mt][3], pal[mt][3]);
            }
#pragma unroll
            for (int np = 0; np < 4; np++) {
                uint32_t bh[4], bl[4];
                LDSM4(bh[0], bh[1], bh[2], bh[3],
                      vh + SWZ((brow + np * 16) * 128 + ks * 32 + bcb));
                LDSM4(bl[0], bl[1], bl[2], bl[3],
                      vl + SWZ((brow + np * 16) * 128 + ks * 32 + bcb));
#pragma unroll
                for (int mt = 0; mt < 2; mt++) {
                    MMA(Oacc[mt][np * 2],     pah[mt], bh[0], bh[1]);
                    MMA(Oacc[mt][np * 2 + 1], pah[mt], bh[2], bh[3]);
                    MMA(Oacc[mt][np * 2],     pah[mt], bl[0], bl[1]);
                    MMA(Oacc[mt][np * 2 + 1], pah[mt], bl[2], bl[3]);
                    MMA(Oacc[mt][np * 2],     pal[mt], bh[0], bh[1]);
                    MMA(Oacc[mt][np * 2 + 1], pal[mt], bh[2], bh[3]);
                }
            }
        }
        __syncthreads();
    }

    // ---- split-k merge (warp_kn 0 vs 1) and O write
    float* mpart = (float*)(smem + F_MPART);
    float* lpart = (float*)(smem + F_LPART);
    float* Opart = (float*)(smem + F_OPART);

    if (warp_kn == 1) {
#pragma unroll
        for (int mt = 0; mt < 2; mt++)
#pragma unroll
            for (int h2 = 0; h2 < 2; h2++) {
                int row = warp_m * 32 + mt * 16 + h2 * 8 + (lane >> 2);
                if ((lane & 3) == 0) {
                    mpart[row] = mrow[mt][h2];
                    lpart[row] = lrow[mt][h2];
                }
#pragma unroll
                for (int nt = 0; nt < 8; nt++) {
                    int col = nt * 8 + (lane & 3) * 2;
                    *(float2*)&Opart[row * 64 + col] =
                        make_float2(Oacc[mt][nt][h2 * 2], Oacc[mt][nt][h2 * 2 + 1]);
                }
            }
    }
    __syncthreads();
    if (warp_kn == 0) {
#pragma unroll
        for (int mt = 0; mt < 2; mt++)
#pragma unroll
            for (int h2 = 0; h2 < 2; h2++) {
                int row = warp_m * 32 + mt * 16 + h2 * 8 + (lane >> 2);
                float m1 = mpart[row], l1 = lpart[row];
                float m0_ = mrow[mt][h2], l0 = lrow[mt][h2];
                float mf = fmaxf(m0_, m1);
                float a0 = __expf(m0_ - mf), a1 = __expf(m1 - mf);
                float inv = 1.f / (l0 * a0 + l1 * a1);
                float* op = g_obuf + ((size_t)z * SEQ + m0 + row) * HDIM;
#pragma unroll
                for (int nt = 0; nt < 8; nt++) {
                    int col = nt * 8 + (lane & 3) * 2;
                    float2 o1 = *(float2*)&Opart[row * 64 + col];
                    *(float2*)&op[col] = make_float2(
                        (Oacc[mt][nt][h2 * 2]     * a0 + o1.x * a1) * inv,
                        (Oacc[mt][nt][h2 * 2 + 1] * a0 + o1.y * a1) * inv);
                }
            }
    }
}

// ---------------------------------------------------------------------------
// Pass 3: output projection.  grid (4, 64), 256 thr, 8 chunks of K=64.
// ---------------------------------------------------------------------------
__global__ __launch_bounds__(256) void out_mma(const float* __restrict__ Hk,
                                               float* __restrict__ Out)
{
    extern __shared__ char smem[];
    uint32_t sb = smem_u32(smem);
    const int tid = threadIdx.x, wid = tid >> 5, lane = tid & 31;
    const int m0 = blockIdx.y * 128, c0 = blockIdx.x * 128;
    const int r = tid >> 1, half = (tid & 1) * 32;
    const int m = m0 + r, b = m >> 11, s = m & (SEQ - 1);

    float acc[2][8][4];
#pragma unroll
    for (int i = 0; i < 2; i++)
#pragma unroll
        for (int j = 0; j < 8; j++)
#pragma unroll
            for (int q = 0; q < 4; q++) acc[i][j][q] = 0.f;

    for (int chunk = 0; chunk < 8; chunk++) {
        const int e0 = chunk * 64;
        const float* oa = g_obuf + ((size_t)(b * HEADS + chunk) * SEQ + s) * HDIM + half;
#pragma unroll
        for (int g = 0; g < 4; g++) {
            float4 u = *(const float4*)(oa + g * 8);
            float4 w = *(const float4*)(oa + g * 8 + 4);
            uint4 hi, lo; pack8(u, w, hi, lo);
            int off = SWZ(r * 128 + (half + g * 8) * 2);
            *(uint4*)(smem + SOFF_A_HI + off) = hi;
            *(uint4*)(smem + SOFF_A_LO + off) = lo;
        }
        const float* hp = Hk + (size_t)(e0 + half) * DM + c0 + r;
#pragma unroll
        for (int dg = 0; dg < 4; dg++) {
            float v[8];
#pragma unroll
            for (int e = 0; e < 8; e++) v[e] = hp[(size_t)(dg * 8 + e) * DM];
            uint4 hi, lo;
            pack8(make_float4(v[0], v[1], v[2], v[3]),
                  make_float4(v[4], v[5], v[6], v[7]), hi, lo);
            int off = SWZ(r * 128 + (half + dg * 8) * 2);
            *(uint4*)(smem + SOFF_B_HI + off) = hi;
            *(uint4*)(smem + SOFF_B_LO + off) = lo;
        }
        __syncthreads();
        compute_tile(sb + SOFF_A_HI, sb + SOFF_A_LO, sb + SOFF_B_HI, sb + SOFF_B_LO,
                     lane, wid & 3, wid >> 2, acc);
        __syncthreads();
    }

    const int warp_m = wid & 3, warp_n = wid >> 2;
#pragma unroll
    for (int mt = 0; mt < 2; mt++)
#pragma unroll
        for (int h2 = 0; h2 < 2; h2++) {
            int mm = m0 + warp_m * 32 + mt * 16 + (lane >> 2) + h2 * 8;
#pragma unroll
            for (int nt = 0; nt < 8; nt++) {
                int c = c0 + warp_n * 64 + nt * 8 + (lane & 3) * 2;
                *(float2*)&Out[(size_t)mm * DM + c] =
                    make_float2(acc[mt][nt][h2 * 2], acc[mt][nt][h2 * 2 + 1]);
            }
        }
}

// ---------------------------------------------------------------------------
extern "C" void kernel_launch(void* const* d_in, const int* in_sizes, int n_in,
                              void* d_out, int out_size)
{
    const float* x  = (const float*)d_in[0];
    const float* w  = (const float*)d_in[1];
    const float* hk = (const float*)d_in[2];
    float* out = (float*)d_out;

    cudaFuncSetAttribute(qkv_mma, cudaFuncAttributeMaxDynamicSharedMemorySize, SMEM_BYTES);
    cudaFuncSetAttribute(fa_mma,  cudaFuncAttributeMaxDynamicSharedMemorySize, FA_SMEM);
    cudaFuncSetAttribute(out_mma, cudaFuncAttributeMaxDynamicSharedMemorySize, SMEM_BYTES);

    qkv_mma<<<dim3(12, 64), 256, SMEM_BYTES>>>(x, w);
    fa_mma<<<dim3(16, 32), 256, FA_SMEM>>>();
    out_mma<<<dim3(4, 64), 256, SMEM_BYTES>>>(hk, out);
}